// round 1
// baseline (speedup 1.0000x reference)
#include <cuda_runtime.h>

#define B_ 8
#define C_ 64
#define H_ 128
#define W_ 128
#define KK_ 9
#define OFFC 18   // 2*KK
#define HW_ (H_*W_)

// Scratch (allocation-free rule: __device__ globals)
__device__ float g_off[B_ * OFFC * HW_];   // clipped offsets, [b][18][y][x]
__device__ float g_wt[KK_ * C_ * C_];      // weights transposed to [t][c][o]

// ---------------------------------------------------------------------------
// Kernel 0: transpose main-conv weights [o][c][ky][kx] -> [t][c][o]
// ---------------------------------------------------------------------------
__global__ void wt_kernel(const float* __restrict__ w) {
    int i = blockIdx.x * blockDim.x + threadIdx.x;
    if (i >= KK_ * C_ * C_) return;
    int o = i & 63;
    int c = (i >> 6) & 63;
    int t = i >> 12;
    g_wt[i] = w[(o * C_ + c) * KK_ + t];
}

// ---------------------------------------------------------------------------
// Kernel 1: offset conv 5x5, pad 2: off[b,oc,y,x] = sum_{c,ky,kx} x*w + bias,
// clipped to [-1,1].  grid (H, 3 oc-groups of 6, B), block 128 (one row).
// ---------------------------------------------------------------------------
__global__ __launch_bounds__(128) void off_kernel(const float* __restrict__ x,
                                                  const float* __restrict__ ow,
                                                  const float* __restrict__ ob) {
    const int x0 = threadIdx.x;
    const int y  = blockIdx.x;
    const int g  = blockIdx.y;   // 0..2 -> oc = g*6 + j
    const int b  = blockIdx.z;

    __shared__ float ws[C_ * 25 * 6];   // [c][tap][j]  (38400 B)
    __shared__ float bs[6];

    for (int idx = threadIdx.x; idx < C_ * 25 * 6; idx += 128) {
        int j   = idx % 6;
        int tap = (idx / 6) % 25;
        int c   = idx / 150;
        ws[idx] = ow[((g * 6 + j) * C_ + c) * 25 + tap];
    }
    if (threadIdx.x < 6) bs[threadIdx.x] = ob[g * 6 + threadIdx.x];
    __syncthreads();

    float acc[6] = {0.f, 0.f, 0.f, 0.f, 0.f, 0.f};
    const float* xb = x + b * C_ * HW_;

    for (int c = 0; c < C_; c++) {
        const float* xc = xb + c * HW_;
        const float* wc = ws + c * 150;
        #pragma unroll
        for (int ky = 0; ky < 5; ky++) {
            int yy = y + ky - 2;
            if (yy < 0 || yy >= H_) continue;
            const float* xr = xc + yy * W_;
            #pragma unroll
            for (int kx = 0; kx < 5; kx++) {
                int xx = x0 + kx - 2;
                float v = (xx >= 0 && xx < W_) ? xr[xx] : 0.f;
                const float* wp = wc + (ky * 5 + kx) * 6;
                #pragma unroll
                for (int j = 0; j < 6; j++) acc[j] += v * wp[j];
            }
        }
    }

    #pragma unroll
    for (int j = 0; j < 6; j++) {
        float v = acc[j] + bs[j];
        v = fminf(fmaxf(v, -1.f), 1.f);
        g_off[((b * OFFC + g * 6 + j) * H_ + y) * W_ + x0] = v;
    }
}

// ---------------------------------------------------------------------------
// Kernel 2: deformable 3x3 conv using clipped offsets.
// One thread per output pixel, 64 fp32 accumulators (all out channels).
// grid (H, B), block 128 (one row).  Per-tap weight slice [c][o] in smem.
// ---------------------------------------------------------------------------
__global__ __launch_bounds__(128) void deform_kernel(const float* __restrict__ x,
                                                     float* __restrict__ out) {
    const int px = threadIdx.x;
    const int y  = blockIdx.x;
    const int b  = blockIdx.y;

    __shared__ float ws[C_ * C_];   // [c][o] for current tap (16 KB)

    float acc[C_];
    #pragma unroll
    for (int o = 0; o < C_; o++) acc[o] = 0.f;

    const float* xb   = x + b * C_ * HW_;
    const float* offb = g_off + b * OFFC * HW_;
    const int    pix  = y * W_ + px;

    for (int t = 0; t < KK_; t++) {
        __syncthreads();   // protect ws against previous-iteration readers
        for (int idx = threadIdx.x; idx < C_ * C_; idx += 128)
            ws[idx] = g_wt[t * C_ * C_ + idx];
        __syncthreads();

        float dy = offb[(2 * t)     * HW_ + pix];
        float dx = offb[(2 * t + 1) * HW_ + pix];
        int ti = t / 3, tj = t % 3;
        float py  = (float)y  + (float)(ti - 1) + dy;
        float pxf = (float)px + (float)(tj - 1) + dx;

        float y0f = floorf(py),  x0f = floorf(pxf);
        float fy  = py - y0f,    fx  = pxf - x0f;
        int y0 = (int)y0f, x0 = (int)x0f;
        int y1 = y0 + 1,   x1 = x0 + 1;

        bool vy0 = (y0 >= 0) && (y0 < H_);
        bool vy1 = (y1 >= 0) && (y1 < H_);
        bool vx0 = (x0 >= 0) && (x0 < W_);
        bool vx1 = (x1 >= 0) && (x1 < W_);

        float w00 = (1.f - fy) * (1.f - fx) * (float)(vy0 && vx0);
        float w01 = (1.f - fy) * fx         * (float)(vy0 && vx1);
        float w10 = fy * (1.f - fx)         * (float)(vy1 && vx0);
        float w11 = fy * fx                 * (float)(vy1 && vx1);

        int cy0 = min(max(y0, 0), H_ - 1), cy1 = min(max(y1, 0), H_ - 1);
        int cx0 = min(max(x0, 0), W_ - 1), cx1 = min(max(x1, 0), W_ - 1);
        int i00 = cy0 * W_ + cx0, i01 = cy0 * W_ + cx1;
        int i10 = cy1 * W_ + cx0, i11 = cy1 * W_ + cx1;

        for (int c = 0; c < C_; c++) {
            const float* xc = xb + c * HW_;
            float s = w00 * xc[i00] + w01 * xc[i01]
                    + w10 * xc[i10] + w11 * xc[i11];
            const float* wc = ws + c * C_;
            #pragma unroll
            for (int o = 0; o < C_; o++) acc[o] += s * wc[o];
        }
    }

    float* ob = out + b * C_ * HW_ + pix;
    #pragma unroll
    for (int o = 0; o < C_; o++) ob[o * HW_] = acc[o];
}

// ---------------------------------------------------------------------------
extern "C" void kernel_launch(void* const* d_in, const int* in_sizes, int n_in,
                              void* d_out, int out_size) {
    const float* x    = (const float*)d_in[0];   // [8,64,128,128]
    const float* w    = (const float*)d_in[1];   // [64,64,3,3]
    const float* ow   = (const float*)d_in[2];   // [18,64,5,5]
    const float* obia = (const float*)d_in[3];   // [18]
    float* out = (float*)d_out;                  // [8,64,128,128]

    wt_kernel<<<(KK_ * C_ * C_ + 255) / 256, 256>>>(w);

    dim3 g1(H_, 3, B_);
    off_kernel<<<g1, 128>>>(x, ow, obia);

    dim3 g2(H_, B_);
    deform_kernel<<<g2, 128>>>(x, out);
}

// round 4
// speedup vs baseline: 2.1048x; 2.1048x over previous
#include <cuda_runtime.h>
#include <cuda_bf16.h>
#include <cstdint>

#define B_ 8
#define C_ 64
#define H_ 128
#define W_ 128
#define KK_ 9
#define OFFC 18
#define HW_ (H_*W_)

// ---------------------------------------------------------------------------
// helpers
// ---------------------------------------------------------------------------
__device__ __forceinline__ uint32_t smem_u32(const void* p) {
    uint32_t a;
    asm("{ .reg .u64 t; cvta.to.shared.u64 t, %1; cvt.u32.u64 %0, t; }" : "=r"(a) : "l"(p));
    return a;
}
__device__ __forceinline__ void sts128(uint32_t addr, uint4 v) {
    asm volatile("st.shared.v4.b32 [%0], {%1,%2,%3,%4};"
                 :: "r"(addr), "r"(v.x), "r"(v.y), "r"(v.z), "r"(v.w) : "memory");
}
#define LDM4(r, a)                                                              \
    asm volatile("ldmatrix.sync.aligned.m8n8.x4.shared.b16 {%0,%1,%2,%3}, [%4];"\
        : "=r"((r)[0]), "=r"((r)[1]), "=r"((r)[2]), "=r"((r)[3]) : "r"(a))

#define MMA(c, a, b0v, b1v)                                                     \
    asm volatile("mma.sync.aligned.m16n8k16.row.col.f32.bf16.bf16.f32 "         \
        "{%0,%1,%2,%3},{%4,%5,%6,%7},{%8,%9},{%0,%1,%2,%3};"                    \
        : "+f"((c)[0]), "+f"((c)[1]), "+f"((c)[2]), "+f"((c)[3])                \
        : "r"((a)[0]), "r"((a)[1]), "r"((a)[2]), "r"((a)[3]),                   \
          "r"(b0v), "r"(b1v))

// ---------------------------------------------------------------------------
// scratch (__device__ globals: allocation-free rule)
// ---------------------------------------------------------------------------
__device__ float g_off[B_ * OFFC * HW_];             // clipped offsets
__device__ __nv_bfloat16 g_wtb[KK_ * 2 * C_ * C_];   // [t][hi/lo][o][c]
__device__ float g_ow8[3 * C_ * 25 * 8];             // offset w: [g][c][tap][8]

// ---------------------------------------------------------------------------
// Kernel 0a: main-conv weights -> bf16 hi/lo, [t][hi/lo][o][c]
// ---------------------------------------------------------------------------
__global__ void wtb_kernel(const float* __restrict__ w) {
    int i = blockIdx.x * blockDim.x + threadIdx.x;
    if (i >= KK_ * C_ * C_) return;
    int c = i & 63, o = (i >> 6) & 63, t = i >> 12;
    float v = w[(o * C_ + c) * KK_ + t];
    __nv_bfloat16 h = __float2bfloat16(v);
    __nv_bfloat16 l = __float2bfloat16(v - __bfloat162float(h));
    g_wtb[(t * 2 + 0) * 4096 + o * 64 + c] = h;
    g_wtb[(t * 2 + 1) * 4096 + o * 64 + c] = l;
}

// ---------------------------------------------------------------------------
// Kernel 0b: offset-conv weights repack [oc][c][tap] -> [g][c][tap][8]
// ---------------------------------------------------------------------------
__global__ void prep_ow(const float* __restrict__ ow) {
    int i = blockIdx.x * blockDim.x + threadIdx.x;
    if (i >= 3 * C_ * 25 * 8) return;
    int j = i & 7;
    int tap = (i >> 3) % 25;
    int c = (i / 200) % C_;
    int g = i / (C_ * 200);
    float v = 0.f;
    if (j < 6) v = ow[((g * 6 + j) * C_ + c) * 25 + tap];
    g_ow8[i] = v;
}

// ---------------------------------------------------------------------------
// Kernel 1: offset conv 5x5 pad 2, clip [-1,1].
// Block: 128 threads (x), 4 output rows/thread. grid (32, 3, 8).
// Weights in smem [c][tap][8]: one LDS.128 + LDS.64 per (c,tap), broadcast.
// ---------------------------------------------------------------------------
__global__ __launch_bounds__(128) void off_kernel(const float* __restrict__ x,
                                                  const float* __restrict__ ob) {
    extern __shared__ float ws[];   // 12800 floats = 51200 B
    const int x0 = threadIdx.x;
    const int y0 = blockIdx.x * 4;
    const int g  = blockIdx.y;
    const int b  = blockIdx.z;

    {
        const uint4* src = ((const uint4*)g_ow8) + g * 3200;
        uint4* dst = (uint4*)ws;
        for (int k = threadIdx.x; k < 3200; k += 128) dst[k] = src[k];
    }
    __syncthreads();

    float acc[4][6];
    #pragma unroll
    for (int r = 0; r < 4; r++)
        #pragma unroll
        for (int j = 0; j < 6; j++) acc[r][j] = 0.f;

    const float* xb = x + b * C_ * HW_;

    for (int c = 0; c < C_; c++) {
        const float* xc = xb + c * HW_;
        const float* wc = ws + c * 200;
        #pragma unroll
        for (int kx = 0; kx < 5; kx++) {
            int xx = x0 + kx - 2;
            bool vx = (xx >= 0) && (xx < W_);
            float v[9];
            #pragma unroll
            for (int r = 0; r < 9; r++) {
                int yy = y0 + r - 2;
                v[r] = (vx && yy >= 0 && yy < H_) ? xc[yy * W_ + xx] : 0.f;
            }
            #pragma unroll
            for (int ky = 0; ky < 5; ky++) {
                const float* wp = wc + (ky * 5 + kx) * 8;
                float4 w0 = *(const float4*)wp;
                float2 w1 = *(const float2*)(wp + 4);
                #pragma unroll
                for (int r = 0; r < 4; r++) {
                    float vv = v[ky + r];
                    acc[r][0] += vv * w0.x;
                    acc[r][1] += vv * w0.y;
                    acc[r][2] += vv * w0.z;
                    acc[r][3] += vv * w0.w;
                    acc[r][4] += vv * w1.x;
                    acc[r][5] += vv * w1.y;
                }
            }
        }
    }

    float bias[6];
    #pragma unroll
    for (int j = 0; j < 6; j++) bias[j] = ob[g * 6 + j];

    #pragma unroll
    for (int r = 0; r < 4; r++)
        #pragma unroll
        for (int j = 0; j < 6; j++) {
            float v = acc[r][j] + bias[j];
            v = fminf(fmaxf(v, -1.f), 1.f);
            g_off[((b * OFFC + g * 6 + j) * H_ + (y0 + r)) * W_ + x0] = v;
        }
}

// ---------------------------------------------------------------------------
// Kernel 2: deformable conv via mma.sync (bf16 3-term split, f32 accum).
// One CTA = one image row (128 px). A[128x64] sampled hi/lo (smem, stride
// 144B -> conflict-free ldmatrix), B[64x64] per-tap weights hi/lo.
// Warp w: rows w*32..w*32+31, all 64 out channels; acc in registers.
// ---------------------------------------------------------------------------
#define SA_HI 0u
#define SA_LO 18432u
#define SB_HI 36864u
#define SB_LO 46080u
#define DSMEM 55296

__global__ __launch_bounds__(128) void deform_mma_kernel(const float* __restrict__ x,
                                                         float* __restrict__ out) {
    extern __shared__ char sm[];
    const uint32_t sb = smem_u32(sm);
    const int tid = threadIdx.x, l = tid & 31, w = tid >> 5;
    const int y = blockIdx.x, b = blockIdx.y;

    const float* xb   = x + b * C_ * HW_;
    const float* offb = g_off + b * OFFC * HW_;
    const int px  = tid;
    const int pix = y * W_ + px;

    float acc[2][8][4];
    #pragma unroll
    for (int mt = 0; mt < 2; mt++)
        #pragma unroll
        for (int nt = 0; nt < 8; nt++)
            #pragma unroll
            for (int r = 0; r < 4; r++) acc[mt][nt][r] = 0.f;

    for (int t = 0; t < KK_; t++) {
        // ---- B tiles: [o][c] bf16 hi/lo -> smem rows stride 144 ----
        #pragma unroll
        for (int j = 0; j < 8; j++) {
            int id = tid + j * 128;            // 0..1023
            int s   = id >> 9;                 // 0 = hi, 1 = lo
            int row = (id >> 3) & 63;
            int cg  = id & 7;
            uint4 v = ((const uint4*)g_wtb)[(t * 2 + s) * 512 + row * 8 + cg];
            sts128(sb + (s ? SB_LO : SB_HI) + (uint32_t)(row * 144 + cg * 16), v);
        }

        // ---- bilinear sample 64 channels for this thread's pixel ----
        float dy = offb[(2 * t)     * HW_ + pix];
        float dx = offb[(2 * t + 1) * HW_ + pix];
        int ti = t / 3, tj = t % 3;
        float py  = (float)y  + (float)(ti - 1) + dy;
        float pxf = (float)px + (float)(tj - 1) + dx;

        float y0f = floorf(py), x0f = floorf(pxf);
        float fy = py - y0f, fx = pxf - x0f;
        int y0 = (int)y0f, x0 = (int)x0f, y1 = y0 + 1, x1 = x0 + 1;

        bool vy0 = (y0 >= 0) && (y0 < H_);
        bool vy1 = (y1 >= 0) && (y1 < H_);
        bool vx0 = (x0 >= 0) && (x0 < W_);
        bool vx1 = (x1 >= 0) && (x1 < W_);

        float w00 = (1.f - fy) * (1.f - fx) * (float)(vy0 && vx0);
        float w01 = (1.f - fy) * fx         * (float)(vy0 && vx1);
        float w10 = fy * (1.f - fx)         * (float)(vy1 && vx0);
        float w11 = fy * fx                 * (float)(vy1 && vx1);

        int cy0 = min(max(y0, 0), H_ - 1), cy1 = min(max(y1, 0), H_ - 1);
        int cx0 = min(max(x0, 0), W_ - 1), cx1 = min(max(x1, 0), W_ - 1);
        int i00 = cy0 * W_ + cx0, i01 = cy0 * W_ + cx1;
        int i10 = cy1 * W_ + cx0, i11 = cy1 * W_ + cx1;

        #pragma unroll
        for (int cg = 0; cg < 8; cg++) {
            __nv_bfloat16 hv[8], lv[8];
            #pragma unroll
            for (int j = 0; j < 8; j++) {
                const float* xc = xb + (cg * 8 + j) * HW_;
                float s = w00 * xc[i00] + w01 * xc[i01]
                        + w10 * xc[i10] + w11 * xc[i11];
                __nv_bfloat16 h = __float2bfloat16(s);
                hv[j] = h;
                lv[j] = __float2bfloat16(s - __bfloat162float(h));
            }
            uint32_t off = (uint32_t)(px * 144 + cg * 16);
            sts128(sb + SA_HI + off, *(const uint4*)hv);
            sts128(sb + SA_LO + off, *(const uint4*)lv);
        }

        __syncthreads();

        // ---- MMA: acc += Ahi*Bhi + Ahi*Blo + Alo*Bhi over K=64 ----
        uint32_t a_h = sb + SA_HI + (uint32_t)((w * 32 + (l & 15)) * 144 + (l >> 4) * 16);
        uint32_t a_l = a_h + (SA_LO - SA_HI);
        uint32_t b_h = sb + SB_HI + (uint32_t)((l & 15) * 144 + (l >> 4) * 16);
        uint32_t b_l = b_h + (SB_LO - SB_HI);

        #pragma unroll
        for (int k = 0; k < 4; k++) {
            uint32_t ah[2][4], al[2][4], bh[4][4], bl[4][4];
            #pragma unroll
            for (int mt = 0; mt < 2; mt++) {
                LDM4(ah[mt], a_h + mt * (16 * 144) + k * 32);
                LDM4(al[mt], a_l + mt * (16 * 144) + k * 32);
            }
            #pragma unroll
            for (int np = 0; np < 4; np++) {
                LDM4(bh[np], b_h + np * (16 * 144) + k * 32);
                LDM4(bl[np], b_l + np * (16 * 144) + k * 32);
            }
            #pragma unroll
            for (int mt = 0; mt < 2; mt++)
                #pragma unroll
                for (int nt = 0; nt < 8; nt++) {
                    int np = nt >> 1, h = nt & 1;
                    MMA(acc[mt][nt], ah[mt], bh[np][h], bh[np][h + 2]);
                    MMA(acc[mt][nt], ah[mt], bl[np][h], bl[np][h + 2]);
                    MMA(acc[mt][nt], al[mt], bh[np][h], bh[np][h + 2]);
                }
        }
        __syncthreads();   // mma reads done before next tap overwrites smem
    }

    // ---- epilogue: c-frag (row = pixel x, col = out channel o) ----
    #pragma unroll
    for (int mt = 0; mt < 2; mt++)
        #pragma unroll
        for (int nt = 0; nt < 8; nt++) {
            int row = w * 32 + mt * 16 + (l >> 2);
            int o   = nt * 8 + (l & 3) * 2;
            float* p = out + b * C_ * HW_ + o * HW_ + y * W_ + row;
            p[0]       = acc[mt][nt][0];
            p[HW_]     = acc[mt][nt][1];
            p[8]       = acc[mt][nt][2];
            p[HW_ + 8] = acc[mt][nt][3];
        }
}

// ---------------------------------------------------------------------------
extern "C" void kernel_launch(void* const* d_in, const int* in_sizes, int n_in,
                              void* d_out, int out_size) {
    const float* x    = (const float*)d_in[0];   // [8,64,128,128]
    const float* w    = (const float*)d_in[1];   // [64,64,3,3]
    const float* ow   = (const float*)d_in[2];   // [18,64,5,5]
    const float* obia = (const float*)d_in[3];   // [18]
    float* out = (float*)d_out;

    cudaFuncSetAttribute(off_kernel,
                         cudaFuncAttributeMaxDynamicSharedMemorySize, 51200);
    cudaFuncSetAttribute(deform_mma_kernel,
                         cudaFuncAttributeMaxDynamicSharedMemorySize, DSMEM);

    wtb_kernel<<<(KK_ * C_ * C_ + 255) / 256, 256>>>(w);
    prep_ow<<<(3 * C_ * 25 * 8 + 255) / 256, 256>>>(ow);

    dim3 g1(32, 3, B_);
    off_kernel<<<g1, 128, 51200>>>(x, obia);

    dim3 g2(H_, B_);
    deform_mma_kernel<<<g2, 128, DSMEM>>>(x, out);
}

// round 5
// speedup vs baseline: 2.6650x; 1.2661x over previous
#include <cuda_runtime.h>
#include <cuda_bf16.h>
#include <cstdint>

#define B_ 8
#define C_ 64
#define H_ 128
#define W_ 128
#define KK_ 9
#define OFFC 18
#define HW_ (H_*W_)

// ---------------------------------------------------------------------------
// helpers
// ---------------------------------------------------------------------------
__device__ __forceinline__ uint32_t smem_u32(const void* p) {
    uint32_t a;
    asm("{ .reg .u64 t; cvta.to.shared.u64 t, %1; cvt.u32.u64 %0, t; }" : "=r"(a) : "l"(p));
    return a;
}
__device__ __forceinline__ void sts128(uint32_t addr, uint4 v) {
    asm volatile("st.shared.v4.b32 [%0], {%1,%2,%3,%4};"
                 :: "r"(addr), "r"(v.x), "r"(v.y), "r"(v.z), "r"(v.w) : "memory");
}
#define LDM4(r, a)                                                              \
    asm volatile("ldmatrix.sync.aligned.m8n8.x4.shared.b16 {%0,%1,%2,%3}, [%4];"\
        : "=r"((r)[0]), "=r"((r)[1]), "=r"((r)[2]), "=r"((r)[3]) : "r"(a))

#define MMA(c, a, b0v, b1v)                                                     \
    asm volatile("mma.sync.aligned.m16n8k16.row.col.f32.bf16.bf16.f32 "         \
        "{%0,%1,%2,%3},{%4,%5,%6,%7},{%8,%9},{%0,%1,%2,%3};"                    \
        : "+f"((c)[0]), "+f"((c)[1]), "+f"((c)[2]), "+f"((c)[3])                \
        : "r"((a)[0]), "r"((a)[1]), "r"((a)[2]), "r"((a)[3]),                   \
          "r"(b0v), "r"(b1v))

// ---------------------------------------------------------------------------
// scratch (__device__ globals: allocation-free rule)
// ---------------------------------------------------------------------------
__device__ float g_off[B_ * OFFC * HW_];               // clipped offsets
__device__ __nv_bfloat16 g_wtb[KK_ * 2 * C_ * C_];     // [t][hi/lo][o][c]
__device__ __nv_bfloat16 g_owb[25 * 2 * 32 * C_];      // [tap][hi/lo][oc32pad][c]
__device__ __nv_bfloat16 g_xt_hi[B_ * H_ * W_ * C_];   // x transposed [b][y][px][c]
__device__ __nv_bfloat16 g_xt_lo[B_ * H_ * W_ * C_];

// ---------------------------------------------------------------------------
// Kernel 0a: main-conv weights -> bf16 hi/lo, [t][hi/lo][o][c]
// ---------------------------------------------------------------------------
__global__ void wtb_kernel(const float* __restrict__ w) {
    int i = blockIdx.x * blockDim.x + threadIdx.x;
    if (i >= KK_ * C_ * C_) return;
    int c = i & 63, o = (i >> 6) & 63, t = i >> 12;
    float v = w[(o * C_ + c) * KK_ + t];
    __nv_bfloat16 h = __float2bfloat16(v);
    __nv_bfloat16 l = __float2bfloat16(v - __bfloat162float(h));
    g_wtb[(t * 2 + 0) * 4096 + o * 64 + c] = h;
    g_wtb[(t * 2 + 1) * 4096 + o * 64 + c] = l;
}

// ---------------------------------------------------------------------------
// Kernel 0b: offset-conv weights -> bf16 hi/lo, [tap][s][oc32(zero-pad)][c]
// ---------------------------------------------------------------------------
__global__ void prep_owb(const float* __restrict__ ow) {
    int i = blockIdx.x * blockDim.x + threadIdx.x;
    if (i >= 25 * 2 * 32 * C_) return;
    int c = i & 63, oc = (i >> 6) & 31, s = (i >> 11) & 1, tap = i >> 12;
    float v = (oc < OFFC) ? ow[(oc * C_ + c) * 25 + tap] : 0.f;
    __nv_bfloat16 h = __float2bfloat16(v);
    g_owb[i] = s ? __float2bfloat16(v - __bfloat162float(h)) : h;
}

// ---------------------------------------------------------------------------
// Kernel 0c: transpose x -> [b][y][px][c] bf16 hi/lo
// grid (H, B), 128 threads = px
// ---------------------------------------------------------------------------
__global__ __launch_bounds__(128) void prep_xt(const float* __restrict__ x) {
    const int px = threadIdx.x, y = blockIdx.x, b = blockIdx.y;
    const float* xs = x + (b * C_ * H_ + y) * W_ + px;
    size_t dst = ((size_t)(b * H_ + y) * W_ + px) * C_;
    #pragma unroll
    for (int cg = 0; cg < 8; cg++) {
        __nv_bfloat16 hv[8], lv[8];
        #pragma unroll
        for (int j = 0; j < 8; j++) {
            float v = xs[(cg * 8 + j) * HW_];
            __nv_bfloat16 h = __float2bfloat16(v);
            hv[j] = h;
            lv[j] = __float2bfloat16(v - __bfloat162float(h));
        }
        *(uint4*)(g_xt_hi + dst + cg * 8) = *(const uint4*)hv;
        *(uint4*)(g_xt_lo + dst + cg * 8) = *(const uint4*)lv;
    }
}

// ---------------------------------------------------------------------------
// Kernel 1: offset conv 5x5 pad 2 via mma.sync, clip [-1,1].
// CTA = one output row y (M=128 px), N=24 oc (pad 32), K=64c per tap.
// A tile: xt row (y+ky-2), px window [-2..129] -> 132 rows, stride 144.
// kx shift = +kx rows in A (alignment preserved by channels-last layout).
// ---------------------------------------------------------------------------
#define OA_HI 0u
#define OA_LO 19008u
#define OB_HI 38016u
#define OB_LO 61056u
#define OSMEM 84096

__global__ __launch_bounds__(128) void off_mma_kernel(const float* __restrict__ ob) {
    extern __shared__ char sm[];
    const uint32_t sb = smem_u32(sm);
    const int tid = threadIdx.x, l = tid & 31, w = tid >> 5;
    const int y = blockIdx.x, b = blockIdx.y;

    float acc[2][3][4];
    #pragma unroll
    for (int mt = 0; mt < 2; mt++)
        #pragma unroll
        for (int nt = 0; nt < 3; nt++)
            #pragma unroll
            for (int r = 0; r < 4; r++) acc[mt][nt][r] = 0.f;

    for (int ky = 0; ky < 5; ky++) {
        int yy = y + ky - 2;
        if (yy < 0 || yy >= H_) continue;     // uniform across block

        __syncthreads();   // previous iteration's reads complete

        // ---- fill A: 132 rows x 8 uint4, hi then lo ----
        const uint4* hsrc = (const uint4*)(g_xt_hi + (size_t)(b * H_ + yy) * W_ * C_);
        const uint4* lsrc = (const uint4*)(g_xt_lo + (size_t)(b * H_ + yy) * W_ * C_);
        for (int idx = tid; idx < 2112; idx += 128) {
            int s = idx >= 1056;
            int id = s ? idx - 1056 : idx;
            int row = id >> 3, q = id & 7;
            int px = row - 2;
            uint4 v = make_uint4(0u, 0u, 0u, 0u);
            if (px >= 0 && px < W_) v = (s ? lsrc : hsrc)[px * 8 + q];
            sts128(sb + (s ? OA_LO : OA_HI) + (uint32_t)(row * 144 + q * 16), v);
        }
        // ---- fill B: 5 taps of this ky, [32oc][64c] hi/lo, stride 144 ----
        for (int idx = tid; idx < 2560; idx += 128) {
            int tap = idx / 512;
            int r = idx - tap * 512;
            int s = r >= 256;
            int id = r & 255;
            int oc = id >> 3, q = id & 7;
            uint4 v = ((const uint4*)g_owb)[((ky * 5 + tap) * 2 + s) * 256 + id];
            sts128(sb + (s ? OB_LO : OB_HI) + (uint32_t)(tap * 4608 + oc * 144 + q * 16), v);
        }
        __syncthreads();

        const uint32_t a_hb = sb + OA_HI + (uint32_t)((w * 32 + (l & 15)) * 144 + (l >> 4) * 16);
        const uint32_t a_lb = a_hb + (OA_LO - OA_HI);
        const uint32_t b_hb = sb + OB_HI + (uint32_t)((l & 15) * 144 + (l >> 4) * 16);
        const uint32_t b_lb = b_hb + (OB_LO - OB_HI);

        #pragma unroll
        for (int kx = 0; kx < 5; kx++) {
            #pragma unroll
            for (int cc = 0; cc < 4; cc++) {
                uint32_t ah[2][4], al[2][4], bh[2][4], bl[2][4];
                #pragma unroll
                for (int mt = 0; mt < 2; mt++) {
                    LDM4(ah[mt], a_hb + (uint32_t)((mt * 16 + kx) * 144 + cc * 32));
                    LDM4(al[mt], a_lb + (uint32_t)((mt * 16 + kx) * 144 + cc * 32));
                }
                #pragma unroll
                for (int np = 0; np < 2; np++) {
                    LDM4(bh[np], b_hb + (uint32_t)(kx * 4608 + np * 2304 + cc * 32));
                    LDM4(bl[np], b_lb + (uint32_t)(kx * 4608 + np * 2304 + cc * 32));
                }
                #pragma unroll
                for (int mt = 0; mt < 2; mt++)
                    #pragma unroll
                    for (int nt = 0; nt < 3; nt++) {
                        int np = nt >> 1, h = nt & 1;
                        MMA(acc[mt][nt], ah[mt], bh[np][h], bh[np][h + 2]);
                        MMA(acc[mt][nt], ah[mt], bl[np][h], bl[np][h + 2]);
                        MMA(acc[mt][nt], al[mt], bh[np][h], bh[np][h + 2]);
                    }
            }
        }
    }

    // ---- epilogue: bias + clip, write valid oc < 18 ----
    #pragma unroll
    for (int mt = 0; mt < 2; mt++)
        #pragma unroll
        for (int nt = 0; nt < 3; nt++) {
            int px0 = w * 32 + mt * 16 + (l >> 2);
            int oc0 = nt * 8 + (l & 3) * 2;
            #pragma unroll
            for (int r = 0; r < 4; r++) {
                int oc = oc0 + (r & 1);
                int px = px0 + (r >> 1) * 8;
                if (oc < OFFC) {
                    float v = acc[mt][nt][r] + ob[oc];
                    v = fminf(fmaxf(v, -1.f), 1.f);
                    g_off[((b * OFFC + oc) * H_ + y) * W_ + px] = v;
                }
            }
        }
}

// ---------------------------------------------------------------------------
// Kernel 2: deformable conv via mma.sync (unchanged from R4, passing).
// ---------------------------------------------------------------------------
#define SA_HI 0u
#define SA_LO 18432u
#define SB_HI 36864u
#define SB_LO 46080u
#define DSMEM 55296

__global__ __launch_bounds__(128) void deform_mma_kernel(const float* __restrict__ x,
                                                         float* __restrict__ out) {
    extern __shared__ char sm[];
    const uint32_t sb = smem_u32(sm);
    const int tid = threadIdx.x, l = tid & 31, w = tid >> 5;
    const int y = blockIdx.x, b = blockIdx.y;

    const float* xb   = x + b * C_ * HW_;
    const float* offb = g_off + b * OFFC * HW_;
    const int px  = tid;
    const int pix = y * W_ + px;

    float acc[2][8][4];
    #pragma unroll
    for (int mt = 0; mt < 2; mt++)
        #pragma unroll
        for (int nt = 0; nt < 8; nt++)
            #pragma unroll
            for (int r = 0; r < 4; r++) acc[mt][nt][r] = 0.f;

    for (int t = 0; t < KK_; t++) {
        #pragma unroll
        for (int j = 0; j < 8; j++) {
            int id = tid + j * 128;
            int s   = id >> 9;
            int row = (id >> 3) & 63;
            int cg  = id & 7;
            uint4 v = ((const uint4*)g_wtb)[(t * 2 + s) * 512 + row * 8 + cg];
            sts128(sb + (s ? SB_LO : SB_HI) + (uint32_t)(row * 144 + cg * 16), v);
        }

        float dy = offb[(2 * t)     * HW_ + pix];
        float dx = offb[(2 * t + 1) * HW_ + pix];
        int ti = t / 3, tj = t % 3;
        float py  = (float)y  + (float)(ti - 1) + dy;
        float pxf = (float)px + (float)(tj - 1) + dx;

        float y0f = floorf(py), x0f = floorf(pxf);
        float fy = py - y0f, fx = pxf - x0f;
        int y0 = (int)y0f, x0 = (int)x0f, y1 = y0 + 1, x1 = x0 + 1;

        bool vy0 = (y0 >= 0) && (y0 < H_);
        bool vy1 = (y1 >= 0) && (y1 < H_);
        bool vx0 = (x0 >= 0) && (x0 < W_);
        bool vx1 = (x1 >= 0) && (x1 < W_);

        float w00 = (1.f - fy) * (1.f - fx) * (float)(vy0 && vx0);
        float w01 = (1.f - fy) * fx         * (float)(vy0 && vx1);
        float w10 = fy * (1.f - fx)         * (float)(vy1 && vx0);
        float w11 = fy * fx                 * (float)(vy1 && vx1);

        int cy0 = min(max(y0, 0), H_ - 1), cy1 = min(max(y1, 0), H_ - 1);
        int cx0 = min(max(x0, 0), W_ - 1), cx1 = min(max(x1, 0), W_ - 1);
        int i00 = cy0 * W_ + cx0, i01 = cy0 * W_ + cx1;
        int i10 = cy1 * W_ + cx0, i11 = cy1 * W_ + cx1;

        #pragma unroll
        for (int cg = 0; cg < 8; cg++) {
            __nv_bfloat16 hv[8], lv[8];
            #pragma unroll
            for (int j = 0; j < 8; j++) {
                const float* xc = xb + (cg * 8 + j) * HW_;
                float s = w00 * xc[i00] + w01 * xc[i01]
                        + w10 * xc[i10] + w11 * xc[i11];
                __nv_bfloat16 h = __float2bfloat16(s);
                hv[j] = h;
                lv[j] = __float2bfloat16(s - __bfloat162float(h));
            }
            uint32_t off = (uint32_t)(px * 144 + cg * 16);
            sts128(sb + SA_HI + off, *(const uint4*)hv);
            sts128(sb + SA_LO + off, *(const uint4*)lv);
        }

        __syncthreads();

        uint32_t a_h = sb + SA_HI + (uint32_t)((w * 32 + (l & 15)) * 144 + (l >> 4) * 16);
        uint32_t a_l = a_h + (SA_LO - SA_HI);
        uint32_t b_h = sb + SB_HI + (uint32_t)((l & 15) * 144 + (l >> 4) * 16);
        uint32_t b_l = b_h + (SB_LO - SB_HI);

        #pragma unroll
        for (int k = 0; k < 4; k++) {
            uint32_t ah[2][4], al[2][4], bh[4][4], bl[4][4];
            #pragma unroll
            for (int mt = 0; mt < 2; mt++) {
                LDM4(ah[mt], a_h + mt * (16 * 144) + k * 32);
                LDM4(al[mt], a_l + mt * (16 * 144) + k * 32);
            }
            #pragma unroll
            for (int np = 0; np < 4; np++) {
                LDM4(bh[np], b_h + np * (16 * 144) + k * 32);
                LDM4(bl[np], b_l + np * (16 * 144) + k * 32);
            }
            #pragma unroll
            for (int mt = 0; mt < 2; mt++)
                #pragma unroll
                for (int nt = 0; nt < 8; nt++) {
                    int np = nt >> 1, h = nt & 1;
                    MMA(acc[mt][nt], ah[mt], bh[np][h], bh[np][h + 2]);
                    MMA(acc[mt][nt], ah[mt], bl[np][h], bl[np][h + 2]);
                    MMA(acc[mt][nt], al[mt], bh[np][h], bh[np][h + 2]);
                }
        }
        __syncthreads();
    }

    #pragma unroll
    for (int mt = 0; mt < 2; mt++)
        #pragma unroll
        for (int nt = 0; nt < 8; nt++) {
            int row = w * 32 + mt * 16 + (l >> 2);
            int o   = nt * 8 + (l & 3) * 2;
            float* p = out + b * C_ * HW_ + o * HW_ + y * W_ + row;
            p[0]       = acc[mt][nt][0];
            p[HW_]     = acc[mt][nt][1];
            p[8]       = acc[mt][nt][2];
            p[HW_ + 8] = acc[mt][nt][3];
        }
}

// ---------------------------------------------------------------------------
extern "C" void kernel_launch(void* const* d_in, const int* in_sizes, int n_in,
                              void* d_out, int out_size) {
    const float* x    = (const float*)d_in[0];   // [8,64,128,128]
    const float* w    = (const float*)d_in[1];   // [64,64,3,3]
    const float* ow   = (const float*)d_in[2];   // [18,64,5,5]
    const float* obia = (const float*)d_in[3];   // [18]
    float* out = (float*)d_out;

    cudaFuncSetAttribute(off_mma_kernel,
                         cudaFuncAttributeMaxDynamicSharedMemorySize, OSMEM);
    cudaFuncSetAttribute(deform_mma_kernel,
                         cudaFuncAttributeMaxDynamicSharedMemorySize, DSMEM);

    wtb_kernel<<<(KK_ * C_ * C_ + 255) / 256, 256>>>(w);
    prep_owb<<<(25 * 2 * 32 * C_ + 255) / 256, 256>>>(ow);

    dim3 gx(H_, B_);
    prep_xt<<<gx, 128>>>(x);

    dim3 g1(H_, B_);
    off_mma_kernel<<<g1, 128, OSMEM>>>(obia);

    dim3 g2(H_, B_);
    deform_mma_kernel<<<g2, 128, DSMEM>>>(x, out);
}